// round 1
// baseline (speedup 1.0000x reference)
#include <cuda_runtime.h>
#include <math.h>

// Tree constants: BRANCH=4, DEPTH=7, DIM=64, ALPHA=16, OUT_DIM=32
// OFFS: L0=0, L1=1, L2=5, L3=21, L4=85, L5=341, L6=1365, L7=5461, N=21845
#define OFF1 1
#define OFF2 5
#define OFF3 21
#define OFF4 85
#define OFF5 341
#define OFF6 1365
#define OFF7 5461

// Packed transposed weights: g_W4[s*1024 + jp*32 + lane] =
//   { W[s][lane][2jp], W[s][lane+32][2jp], W[s][lane][2jp+1], W[s][lane+32][2jp+1] }
__device__ float4 g_W4[16 * 1024];          // 256 KB
__device__ float  g_WtO[64 * 32];           // W_out transposed: [d][o]
__device__ float  g_enc4[256 * 64];         // level-4 encodings
__device__ float  g_enc3[64 * 64];          // level-3 encodings

__device__ __forceinline__ float sigm(float x) {
    return 1.0f / (1.0f + __expf(-x));
}

// Warp-cooperative 64x64 matvec + bias + sigmoid.
// h: 64 floats in shared. dst: 64 floats (shared or global).
// lane i writes dst[i] and dst[i+32]. All loads from g_W4 are coalesced LDG.128.
__device__ __forceinline__ void matvec_sig(int s, const float* __restrict__ bv,
                                           const float* hsh, float* dst, int lane) {
    const float4* wp = g_W4 + s * 1024;
    float acc0 = bv[s * 64 + lane];
    float acc1 = bv[s * 64 + 32 + lane];
#pragma unroll 8
    for (int jp = 0; jp < 32; jp++) {
        float4 w = wp[jp * 32 + lane];
        float2 h2 = *(const float2*)(hsh + 2 * jp);
        acc0 = fmaf(w.x, h2.x, acc0);
        acc1 = fmaf(w.y, h2.x, acc1);
        acc0 = fmaf(w.z, h2.y, acc0);
        acc1 = fmaf(w.w, h2.y, acc1);
    }
    dst[lane]      = sigm(acc0);
    dst[lane + 32] = sigm(acc1);
}

// ---------------------------------------------------------------------------
// K0: pack W into transposed float4 layout; transpose W_out.
// ---------------------------------------------------------------------------
__global__ void k_prep(const float* __restrict__ W, const float* __restrict__ Wout) {
    int s = blockIdx.x;
    if (s < 16) {
        const float* Ws = W + s * 4096;
        for (int t = threadIdx.x; t < 1024; t += blockDim.x) {
            int jp = t >> 5, i = t & 31;
            float4 v;
            v.x = Ws[i * 64 + 2 * jp];
            v.y = Ws[(i + 32) * 64 + 2 * jp];
            v.z = Ws[i * 64 + 2 * jp + 1];
            v.w = Ws[(i + 32) * 64 + 2 * jp + 1];
            g_W4[s * 1024 + t] = v;
        }
    } else {
        for (int t = threadIdx.x; t < 2048; t += blockDim.x) {
            int d = t >> 5, o = t & 31;
            g_WtO[t] = Wout[o * 64 + d];
        }
    }
}

// ---------------------------------------------------------------------------
// K1: one block per level-4 subtree (256 blocks). Levels 7 -> 6 -> 5 -> 4
// entirely in shared memory, only __syncthreads between levels.
// ---------------------------------------------------------------------------
__global__ void __launch_bounds__(512) k_sub(const int* __restrict__ sym,
                                             const float* __restrict__ bv) {
    __shared__ float sLeaf[64][64];   // 16 KB
    __shared__ float sL6[16][64];     // 4 KB
    __shared__ float sL5[4][64];      // 1 KB
    __shared__ float sH[16][64];      // 4 KB
    __shared__ int   sSym[64];

    int b    = blockIdx.x;
    int tid  = threadIdx.x;
    int w    = tid >> 5;
    int lane = tid & 31;

    if (tid < 64) sSym[tid] = sym[OFF7 + (b << 6) + tid];
    __syncthreads();

    // --- level 7 (leaves): e = sigmoid(b[sym]); h = 0 ---
#pragma unroll
    for (int p = 0; p < 8; p++) {
        int idx = tid + p * 512;
        int k = idx >> 6, d = idx & 63;
        sLeaf[k][d] = sigm(bv[sSym[k] * 64 + d]);
    }
    __syncthreads();

    // --- level 6: 16 nodes, one warp each ---
    {
        int s = sym[OFF6 + (b << 4) + w];
        int r = 4 * w;
        float h0 = 0.25f * (sLeaf[r][lane]      + sLeaf[r + 1][lane] +
                            sLeaf[r + 2][lane]  + sLeaf[r + 3][lane]);
        float h1 = 0.25f * (sLeaf[r][lane + 32] + sLeaf[r + 1][lane + 32] +
                            sLeaf[r + 2][lane + 32] + sLeaf[r + 3][lane + 32]);
        sH[w][lane] = h0; sH[w][lane + 32] = h1;
        __syncwarp();
        matvec_sig(s, bv, sH[w], sL6[w], lane);
    }
    __syncthreads();

    // --- level 5: 4 nodes, warps 0..3 ---
    if (w < 4) {
        int s = sym[OFF5 + (b << 2) + w];
        int r = 4 * w;
        float h0 = 0.25f * (sL6[r][lane]      + sL6[r + 1][lane] +
                            sL6[r + 2][lane]  + sL6[r + 3][lane]);
        float h1 = 0.25f * (sL6[r][lane + 32] + sL6[r + 1][lane + 32] +
                            sL6[r + 2][lane + 32] + sL6[r + 3][lane + 32]);
        sH[w][lane] = h0; sH[w][lane + 32] = h1;
        __syncwarp();
        matvec_sig(s, bv, sH[w], sL5[w], lane);
    }
    __syncthreads();

    // --- level 4: 1 node, warp 0 -> global ---
    if (w == 0) {
        int s = sym[OFF4 + b];
        float h0 = 0.25f * (sL5[0][lane]      + sL5[1][lane] +
                            sL5[2][lane]      + sL5[3][lane]);
        float h1 = 0.25f * (sL5[0][lane + 32] + sL5[1][lane + 32] +
                            sL5[2][lane + 32] + sL5[3][lane + 32]);
        sH[0][lane] = h0; sH[0][lane + 32] = h1;
        __syncwarp();
        matvec_sig(s, bv, sH[0], g_enc4 + b * 64, lane);
    }
}

// ---------------------------------------------------------------------------
// K2: level 3 (64 nodes) — 16 blocks x 4 warps, one warp per node.
// ---------------------------------------------------------------------------
__global__ void __launch_bounds__(128) k_l3(const int* __restrict__ sym,
                                            const float* __restrict__ bv) {
    __shared__ float sH[4][64];
    int w    = threadIdx.x >> 5;
    int lane = threadIdx.x & 31;
    int n    = blockIdx.x * 4 + w;        // 0..63

    int s = sym[OFF3 + n];
    const float* c = g_enc4 + (4 * n) * 64;
    float h0 = 0.25f * (c[lane]       + c[64 + lane]  + c[128 + lane] + c[192 + lane]);
    float h1 = 0.25f * (c[32 + lane]  + c[96 + lane]  + c[160 + lane] + c[224 + lane]);
    sH[w][lane] = h0; sH[w][lane + 32] = h1;
    __syncwarp();
    matvec_sig(s, bv, sH[w], g_enc3 + n * 64, lane);
}

// ---------------------------------------------------------------------------
// K3: levels 2, 1, 0 + output projection. Single block, 16 warps.
// ---------------------------------------------------------------------------
__global__ void __launch_bounds__(512) k_top(const int* __restrict__ sym,
                                             const float* __restrict__ bv,
                                             const float* __restrict__ bout,
                                             float* __restrict__ out) {
    __shared__ float sL2[16][64];
    __shared__ float sL1[4][64];
    __shared__ float sE0[64];
    __shared__ float sH[16][64];

    int tid  = threadIdx.x;
    int w    = tid >> 5;
    int lane = tid & 31;

    // --- level 2: 16 nodes, one warp each (children = level-3 in global) ---
    {
        int s = sym[OFF2 + w];
        const float* c = g_enc3 + (4 * w) * 64;
        float h0 = 0.25f * (c[lane]      + c[64 + lane] + c[128 + lane] + c[192 + lane]);
        float h1 = 0.25f * (c[32 + lane] + c[96 + lane] + c[160 + lane] + c[224 + lane]);
        sH[w][lane] = h0; sH[w][lane + 32] = h1;
        __syncwarp();
        matvec_sig(s, bv, sH[w], sL2[w], lane);
    }
    __syncthreads();

    // --- level 1: 4 nodes ---
    if (w < 4) {
        int s = sym[OFF1 + w];
        int r = 4 * w;
        float h0 = 0.25f * (sL2[r][lane]      + sL2[r + 1][lane] +
                            sL2[r + 2][lane]  + sL2[r + 3][lane]);
        float h1 = 0.25f * (sL2[r][lane + 32] + sL2[r + 1][lane + 32] +
                            sL2[r + 2][lane + 32] + sL2[r + 3][lane + 32]);
        sH[w][lane] = h0; sH[w][lane + 32] = h1;
        __syncwarp();
        matvec_sig(s, bv, sH[w], sL1[w], lane);
    }
    __syncthreads();

    // --- level 0 + output: warp 0 ---
    if (w == 0) {
        int s = sym[0];
        float h0 = 0.25f * (sL1[0][lane]      + sL1[1][lane] +
                            sL1[2][lane]      + sL1[3][lane]);
        float h1 = 0.25f * (sL1[0][lane + 32] + sL1[1][lane + 32] +
                            sL1[2][lane + 32] + sL1[3][lane + 32]);
        sH[0][lane] = h0; sH[0][lane + 32] = h1;
        __syncwarp();
        matvec_sig(s, bv, sH[0], sE0, lane);
        __syncwarp();

        // out[o] = b_out[o] + sum_d W_out[o][d] * e0[d]   (coalesced via g_WtO)
        float acc = bout[lane];
#pragma unroll 16
        for (int d = 0; d < 64; d++)
            acc = fmaf(g_WtO[d * 32 + lane], sE0[d], acc);
        out[lane] = acc;
    }
}

// ---------------------------------------------------------------------------
extern "C" void kernel_launch(void* const* d_in, const int* in_sizes, int n_in,
                              void* d_out, int out_size) {
    // Robust input mapping by element count (all distinct):
    // sym: 21845 (int32), children: 87380 (int32, unused — structure is
    // deterministic: child(l,i) = OFFS[l+1]+4i+c), W: 65536, b: 1024,
    // W_out: 2048, b_out: 32.
    const int*   sym  = nullptr;
    const float* W    = nullptr;
    const float* bv   = nullptr;
    const float* Wout = nullptr;
    const float* bout = nullptr;
    for (int i = 0; i < n_in; i++) {
        switch (in_sizes[i]) {
            case 21845: sym  = (const int*)  d_in[i]; break;
            case 65536: W    = (const float*)d_in[i]; break;
            case 1024:  bv   = (const float*)d_in[i]; break;
            case 2048:  Wout = (const float*)d_in[i]; break;
            case 32:    bout = (const float*)d_in[i]; break;
            default: break; // children (87380) unused
        }
    }
    float* out = (float*)d_out;

    k_prep<<<17, 256>>>(W, Wout);
    k_sub <<<256, 512>>>(sym, bv);
    k_l3  <<<16, 128>>>(sym, bv);
    k_top <<<1, 512>>>(sym, bv, bout, out);
}

// round 3
// speedup vs baseline: 1.3446x; 1.3446x over previous
#include <cuda_runtime.h>
#include <math.h>

// Tree constants: BRANCH=4, DEPTH=7, DIM=64, ALPHA=16, OUT_DIM=32
// OFFS: L0=0, L1=1, L2=5, L3=21, L4=85, L5=341, L6=1365, L7=5461, N=21845
#define OFF1 1
#define OFF2 5
#define OFF3 21
#define OFF4 85
#define OFF5 341
#define OFF6 1365
#define OFF7 5461

// Packed transposed weights: g_W4[s*1024 + jp*32 + lane] =
//   { W[s][lane][2jp], W[s][lane+32][2jp], W[s][lane][2jp+1], W[s][lane+32][2jp+1] }
__device__ float4 g_W4[16 * 1024];          // 256 KB
__device__ float  g_WtO[64 * 32];           // W_out transposed: [d][o]
__device__ float  g_enc4[256 * 64];         // level-4 encodings
__device__ float  g_enc3[64 * 64];          // level-3 encodings

__device__ __forceinline__ float sigm(float x) {
    return 1.0f / (1.0f + __expf(-x));
}

// ---------------------------------------------------------------------------
// Single-warp 64x64 matvec + bias + sigmoid, software-pipelined loads (MLP=8).
// wp = g_W4 + s*1024 (+lane added inside). hsh: 64 floats in shared.
// lane writes dst[lane], dst[lane+32].
// ---------------------------------------------------------------------------
__device__ __forceinline__ void matvec_sig_b(const float4* __restrict__ wpbase,
                                             float b0, float b1,
                                             const float* hsh, float* dst, int lane) {
    const float4* wp = wpbase + lane;
    float4 w[8];
#pragma unroll
    for (int i = 0; i < 8; i++) w[i] = wp[i * 32];
    float acc0 = b0, acc1 = b1;
#pragma unroll
    for (int bt = 0; bt < 4; bt++) {
        float4 wn[8];
        if (bt < 3) {
#pragma unroll
            for (int i = 0; i < 8; i++) wn[i] = wp[(bt + 1) * 256 + i * 32];
        }
        const float2* hp = (const float2*)hsh + bt * 8;
#pragma unroll
        for (int i = 0; i < 8; i++) {
            float2 h2 = hp[i];
            acc0 = fmaf(w[i].x, h2.x, acc0);
            acc1 = fmaf(w[i].y, h2.x, acc1);
            acc0 = fmaf(w[i].z, h2.y, acc0);
            acc1 = fmaf(w[i].w, h2.y, acc1);
        }
        if (bt < 3) {
#pragma unroll
            for (int i = 0; i < 8; i++) w[i] = wn[i];
        }
    }
    dst[lane]      = sigm(acc0);
    dst[lane + 32] = sigm(acc1);
}

// K-split partial: warp q (0..3) of a 4-warp group handles jp = q*8 .. q*8+7
// (8 loads, all in flight -> one L2 round trip). Partial accs out.
__device__ __forceinline__ void matvec_part4(const float4* __restrict__ wpbase,
                                             const float* hsh, int q, int lane,
                                             float& p0, float& p1) {
    const float4* wp = wpbase + q * 256 + lane;
    float4 w[8];
#pragma unroll
    for (int i = 0; i < 8; i++) w[i] = wp[i * 32];
    const float2* hp = (const float2*)hsh + q * 8;
    float a0 = 0.f, a1 = 0.f;
#pragma unroll
    for (int i = 0; i < 8; i++) {
        float2 h2 = hp[i];
        a0 = fmaf(w[i].x, h2.x, a0);
        a1 = fmaf(w[i].y, h2.x, a1);
        a0 = fmaf(w[i].z, h2.y, a0);
        a1 = fmaf(w[i].w, h2.y, a1);
    }
    p0 = a0; p1 = a1;
}

// ---------------------------------------------------------------------------
// K0: pack W into transposed float4 layout; transpose W_out.
// ---------------------------------------------------------------------------
__global__ void k_prep(const float* __restrict__ W, const float* __restrict__ Wout) {
    int s = blockIdx.x;
    if (s < 16) {
        const float* Ws = W + s * 4096;
        for (int t = threadIdx.x; t < 1024; t += blockDim.x) {
            int jp = t >> 5, i = t & 31;
            float4 v;
            v.x = Ws[i * 64 + 2 * jp];
            v.y = Ws[(i + 32) * 64 + 2 * jp];
            v.z = Ws[i * 64 + 2 * jp + 1];
            v.w = Ws[(i + 32) * 64 + 2 * jp + 1];
            g_W4[s * 1024 + t] = v;
        }
    } else {
        for (int t = threadIdx.x; t < 2048; t += blockDim.x) {
            int d = t >> 5, o = t & 31;
            g_WtO[t] = Wout[o * 64 + d];
        }
    }
}

// ---------------------------------------------------------------------------
// K1: one block per level-4 subtree (256 blocks). Levels 7 -> 6 -> 5 -> 4.
// ---------------------------------------------------------------------------
__global__ void __launch_bounds__(512) k_sub(const int* __restrict__ sym,
                                             const float* __restrict__ bv) {
    __shared__ float sLeaf[64][64];   // 16 KB
    __shared__ float sL6[16][64];     // 4 KB
    __shared__ float sL5[4][64];      // 1 KB
    __shared__ float sH[16][64];      // 4 KB
    __shared__ float sP[16][64];      // 4 KB  K-split partials
    __shared__ float sBv[16 * 64];    // 4 KB
    __shared__ int   sSym[64];

    int b    = blockIdx.x;
    int tid  = threadIdx.x;
    int w    = tid >> 5;
    int lane = tid & 31;

    if (tid < 64) sSym[tid] = sym[OFF7 + (b << 6) + tid];
    // preload biases (4KB): 2 floats/thread, single round trip
    sBv[tid]       = bv[tid];
    sBv[tid + 512] = bv[tid + 512];
    __syncthreads();

    // --- level 7 (leaves): e = sigmoid(b[sym]) ---
#pragma unroll
    for (int p = 0; p < 8; p++) {
        int idx = tid + p * 512;
        int k = idx >> 6, d = idx & 63;
        sLeaf[k][d] = sigm(sBv[sSym[k] * 64 + d]);
    }
    __syncthreads();

    // --- level 6: 16 nodes, one warp each ---
    {
        int s = sym[OFF6 + (b << 4) + w];
        int r = 4 * w;
        float h0 = 0.25f * (sLeaf[r][lane]      + sLeaf[r + 1][lane] +
                            sLeaf[r + 2][lane]  + sLeaf[r + 3][lane]);
        float h1 = 0.25f * (sLeaf[r][lane + 32] + sLeaf[r + 1][lane + 32] +
                            sLeaf[r + 2][lane + 32] + sLeaf[r + 3][lane + 32]);
        sH[w][lane] = h0; sH[w][lane + 32] = h1;
        __syncwarp();
        matvec_sig_b(g_W4 + s * 1024, sBv[s * 64 + lane], sBv[s * 64 + 32 + lane],
                     sH[w], sL6[w], lane);
    }
    __syncthreads();

    // --- level 5: 4 nodes, K-split across 4 warps each (16 warps busy) ---
    {
        int g = w >> 2, q = w & 3;                 // group g -> node g
        if (q == 0) {
            int r = 4 * g;
            sH[g][lane]      = 0.25f * (sL6[r][lane]      + sL6[r + 1][lane] +
                                        sL6[r + 2][lane]  + sL6[r + 3][lane]);
            sH[g][lane + 32] = 0.25f * (sL6[r][lane + 32] + sL6[r + 1][lane + 32] +
                                        sL6[r + 2][lane + 32] + sL6[r + 3][lane + 32]);
        }
    }
    __syncthreads();
    {
        int g = w >> 2, q = w & 3;
        int s = sym[OFF5 + (b << 2) + g];
        float p0, p1;
        matvec_part4(g_W4 + s * 1024, sH[g], q, lane, p0, p1);
        sP[w][lane] = p0; sP[w][lane + 32] = p1;
    }
    __syncthreads();
    if (w < 4) {                                   // warp w reduces node w
        int s = sym[OFF5 + (b << 2) + w];
        int r = 4 * w;
        float r0 = sP[r][lane]      + sP[r + 1][lane]      + sP[r + 2][lane]      + sP[r + 3][lane];
        float r1 = sP[r][lane + 32] + sP[r + 1][lane + 32] + sP[r + 2][lane + 32] + sP[r + 3][lane + 32];
        sL5[w][lane]      = sigm(r0 + sBv[s * 64 + lane]);
        sL5[w][lane + 32] = sigm(r1 + sBv[s * 64 + 32 + lane]);
    }
    __syncthreads();

    // --- level 4: 1 node, K-split across warps 0..3 ---
    if (w == 0) {
        sH[0][lane]      = 0.25f * (sL5[0][lane]      + sL5[1][lane] +
                                    sL5[2][lane]      + sL5[3][lane]);
        sH[0][lane + 32] = 0.25f * (sL5[0][lane + 32] + sL5[1][lane + 32] +
                                    sL5[2][lane + 32] + sL5[3][lane + 32]);
    }
    __syncthreads();
    if (w < 4) {
        int s = sym[OFF4 + b];
        float p0, p1;
        matvec_part4(g_W4 + s * 1024, sH[0], w, lane, p0, p1);
        sP[w][lane] = p0; sP[w][lane + 32] = p1;
    }
    __syncthreads();
    if (w == 0) {
        int s = sym[OFF4 + b];
        float r0 = sP[0][lane]      + sP[1][lane]      + sP[2][lane]      + sP[3][lane];
        float r1 = sP[0][lane + 32] + sP[1][lane + 32] + sP[2][lane + 32] + sP[3][lane + 32];
        g_enc4[b * 64 + lane]      = sigm(r0 + sBv[s * 64 + lane]);
        g_enc4[b * 64 + 32 + lane] = sigm(r1 + sBv[s * 64 + 32 + lane]);
    }
}

// ---------------------------------------------------------------------------
// K2: level 3 (64 nodes) — 16 blocks x 4 warps, one warp per node.
// ---------------------------------------------------------------------------
__global__ void __launch_bounds__(128) k_l3(const int* __restrict__ sym,
                                            const float* __restrict__ bv) {
    __shared__ float sH[4][64];
    int w    = threadIdx.x >> 5;
    int lane = threadIdx.x & 31;
    int n    = blockIdx.x * 4 + w;        // 0..63

    int s = sym[OFF3 + n];
    const float* c = g_enc4 + (4 * n) * 64;
    float h0 = 0.25f * (c[lane]       + c[64 + lane]  + c[128 + lane] + c[192 + lane]);
    float h1 = 0.25f * (c[32 + lane]  + c[96 + lane]  + c[160 + lane] + c[224 + lane]);
    sH[w][lane] = h0; sH[w][lane + 32] = h1;
    __syncwarp();
    matvec_sig_b(g_W4 + s * 1024, bv[s * 64 + lane], bv[s * 64 + 32 + lane],
                 sH[w], g_enc3 + n * 64, lane);
}

// ---------------------------------------------------------------------------
// K3: levels 2, 1, 0 + output projection. Single block, 16 warps.
// ---------------------------------------------------------------------------
__global__ void __launch_bounds__(512) k_top(const int* __restrict__ sym,
                                             const float* __restrict__ bv,
                                             const float* __restrict__ bout,
                                             float* __restrict__ out) {
    __shared__ float sL2[16][64];
    __shared__ float sL1[4][64];
    __shared__ float sE0[64];
    __shared__ float sH[16][64];
    __shared__ float sP[16][64];
    __shared__ float sBv[16 * 64];     // 4 KB
    __shared__ float sWtO[64 * 32];    // 8 KB
    __shared__ float sOP[4][32];

    int tid  = threadIdx.x;
    int w    = tid >> 5;
    int lane = tid & 31;

    // preload bv (4KB) and W_out^T (8KB), all loads in flight at once
    sBv[tid]        = bv[tid];
    sBv[tid + 512]  = bv[tid + 512];
    sWtO[tid]       = g_WtO[tid];
    sWtO[tid + 512] = g_WtO[tid + 512];
    sWtO[tid + 1024] = g_WtO[tid + 1024];
    sWtO[tid + 1536] = g_WtO[tid + 1536];
    __syncthreads();

    // --- level 2: 16 nodes, one warp each (children = level-3 in global) ---
    {
        int s = sym[OFF2 + w];
        const float* c = g_enc3 + (4 * w) * 64;
        float h0 = 0.25f * (c[lane]      + c[64 + lane] + c[128 + lane] + c[192 + lane]);
        float h1 = 0.25f * (c[32 + lane] + c[96 + lane] + c[160 + lane] + c[224 + lane]);
        sH[w][lane] = h0; sH[w][lane + 32] = h1;
        __syncwarp();
        matvec_sig_b(g_W4 + s * 1024, sBv[s * 64 + lane], sBv[s * 64 + 32 + lane],
                     sH[w], sL2[w], lane);
    }
    __syncthreads();

    // --- level 1: 4 nodes, K-split across 4 warps each ---
    {
        int g = w >> 2, q = w & 3;
        if (q == 0) {
            int r = 4 * g;
            sH[g][lane]      = 0.25f * (sL2[r][lane]      + sL2[r + 1][lane] +
                                        sL2[r + 2][lane]  + sL2[r + 3][lane]);
            sH[g][lane + 32] = 0.25f * (sL2[r][lane + 32] + sL2[r + 1][lane + 32] +
                                        sL2[r + 2][lane + 32] + sL2[r + 3][lane + 32]);
        }
    }
    __syncthreads();
    {
        int g = w >> 2, q = w & 3;
        int s = sym[OFF1 + g];
        float p0, p1;
        matvec_part4(g_W4 + s * 1024, sH[g], q, lane, p0, p1);
        sP[w][lane] = p0; sP[w][lane + 32] = p1;
    }
    __syncthreads();
    if (w < 4) {
        int s = sym[OFF1 + w];
        int r = 4 * w;
        float r0 = sP[r][lane]      + sP[r + 1][lane]      + sP[r + 2][lane]      + sP[r + 3][lane];
        float r1 = sP[r][lane + 32] + sP[r + 1][lane + 32] + sP[r + 2][lane + 32] + sP[r + 3][lane + 32];
        sL1[w][lane]      = sigm(r0 + sBv[s * 64 + lane]);
        sL1[w][lane + 32] = sigm(r1 + sBv[s * 64 + 32 + lane]);
    }
    __syncthreads();

    // --- level 0: 1 node, K-split across warps 0..3 ---
    if (w == 0) {
        sH[0][lane]      = 0.25f * (sL1[0][lane]      + sL1[1][lane] +
                                    sL1[2][lane]      + sL1[3][lane]);
        sH[0][lane + 32] = 0.25f * (sL1[0][lane + 32] + sL1[1][lane + 32] +
                                    sL1[2][lane + 32] + sL1[3][lane + 32]);
    }
    __syncthreads();
    if (w < 4) {
        int s = sym[0];
        float p0, p1;
        matvec_part4(g_W4 + s * 1024, sH[0], w, lane, p0, p1);
        sP[w][lane] = p0; sP[w][lane + 32] = p1;
    }
    __syncthreads();
    if (w == 0) {
        int s = sym[0];
        float r0 = sP[0][lane]      + sP[1][lane]      + sP[2][lane]      + sP[3][lane];
        float r1 = sP[0][lane + 32] + sP[1][lane + 32] + sP[2][lane + 32] + sP[3][lane + 32];
        sE0[lane]      = sigm(r0 + sBv[s * 64 + lane]);
        sE0[lane + 32] = sigm(r1 + sBv[s * 64 + 32 + lane]);
    }
    __syncthreads();

    // --- output projection: K-split over d across warps 0..3, all from smem ---
    if (w < 4) {
        float acc = 0.f;
#pragma unroll
        for (int i = 0; i < 16; i++) {
            int d = w * 16 + i;
            acc = fmaf(sWtO[d * 32 + lane], sE0[d], acc);
        }
        sOP[w][lane] = acc;   // lane in 0..31
    }
    __syncthreads();
    if (w == 0) {
        out[lane] = bout[lane] + sOP[0][lane] + sOP[1][lane] + sOP[2][lane] + sOP[3][lane];
    }
}

// ---------------------------------------------------------------------------
extern "C" void kernel_launch(void* const* d_in, const int* in_sizes, int n_in,
                              void* d_out, int out_size) {
    const int*   sym  = nullptr;
    const float* W    = nullptr;
    const float* bv   = nullptr;
    const float* Wout = nullptr;
    const float* bout = nullptr;
    for (int i = 0; i < n_in; i++) {
        switch (in_sizes[i]) {
            case 21845: sym  = (const int*)  d_in[i]; break;
            case 65536: W    = (const float*)d_in[i]; break;
            case 1024:  bv   = (const float*)d_in[i]; break;
            case 2048:  Wout = (const float*)d_in[i]; break;
            case 32:    bout = (const float*)d_in[i]; break;
            default: break; // children (87380) unused — structure is deterministic
        }
    }
    float* out = (float*)d_out;

    k_prep<<<17, 256>>>(W, Wout);
    k_sub <<<256, 512>>>(sym, bv);
    k_l3  <<<16, 128>>>(sym, bv);
    k_top <<<1, 512>>>(sym, bv, bout, out);
}